// round 3
// baseline (speedup 1.0000x reference)
#include <cuda_runtime.h>
#include <cstdint>
#include <cstddef>

// ============================================================================
// TensorFusion: out = tanh(tanh(tanh(fusion@W1+b1)@W2+b2)@W3+b3)
// fusion[b, (i,j,k)] = a_h[b,i] * v_h[b,j] * t_h[b,k], each 65-dim ([1, x]).
//
// Kernel 1: out1[b,h] partial sums over i:
//   for each (i, mtile): C[b,h] = sum_j s_j[b] * (sum_k t_h[b,k] * W1[(i,j,k),h])
//   with s_j[b] = a_h[b,i] * v_h[b,j].
// Kernel 2: reduce 65 partials, bias+tanh, two 64x64 layers.
// ============================================================================

#define DL 64
#define DH 65            // DL + 1
#define HID 64
#define BATCH 512
#define MTILE 64         // rows per CTA
#define NMT (BATCH / MTILE)   // 8 M-tiles
#define THREADS 128

// Deterministic partial accumulator: [65][512][64] fp32 = 8.52 MB
__device__ float g_partials[(size_t)DH * BATCH * HID];

// ---- packed f32x2 helpers (Blackwell) --------------------------------------
__device__ __forceinline__ unsigned long long pack2(float lo, float hi) {
    unsigned long long r;
    asm("mov.b64 %0, {%1, %2};" : "=l"(r) : "f"(lo), "f"(hi));
    return r;
}
__device__ __forceinline__ void unpack2(unsigned long long v, float &lo, float &hi) {
    asm("mov.b64 {%0, %1}, %2;" : "=f"(lo), "=f"(hi) : "l"(v));
}
// d = a*b + d   (two fp32 FMAs in one instruction)
__device__ __forceinline__ void fma2(unsigned long long &d,
                                     unsigned long long a,
                                     unsigned long long b) {
    asm("fma.rn.f32x2 %0, %1, %2, %0;" : "+l"(d) : "l"(a), "l"(b));
}

// ============================================================================
// Kernel 1: main contraction.
// grid = (8 mtiles, 65 i-values), block = 128 threads.
// Thread micro-tile: 8 rows x 4 cols. Rows packed in pairs for f32x2.
// smem: Tsm[65][64] (k-major t_h tile), Wsm[65][64] (per-j W1 block), a_col[64]
// ============================================================================
__global__ void __launch_bounds__(THREADS, 4)
fusion_gemm_kernel(const float* __restrict__ l,
                   const float* __restrict__ a,
                   const float* __restrict__ v,
                   const float* __restrict__ W1)
{
    __shared__ float Tsm[DH][MTILE];   // [k][row]
    __shared__ float Wsm[DH][HID];     // [k][h]
    __shared__ float a_col[MTILE];

    const int tid = threadIdx.x;
    const int mt  = blockIdx.x;
    const int i   = blockIdx.y;
    const int b0  = mt * MTILE;

    const int tx = tid & 15;           // 16 col-groups
    const int ty = tid >> 4;           // 8 row-groups
    const int h0 = tx * 4;             // 4 cols
    const int r0 = ty * 8;             // 8 rows

    // ---- load t_h tile (k-major) and a-column ----
    for (int idx = tid; idx < DH * MTILE; idx += THREADS) {
        int k = idx >> 6;              // MTILE == 64
        int r = idx & 63;
        Tsm[k][r] = (k == 0) ? 1.0f : l[(size_t)(b0 + r) * DL + (k - 1)];
    }
    for (int r = tid; r < MTILE; r += THREADS) {
        a_col[r] = (i == 0) ? 1.0f : a[(size_t)(b0 + r) * DL + (i - 1)];
    }

    // ---- accumulators: 4 row-pairs x 4 cols, packed f32x2 ----
    unsigned long long C[4][4];
    #pragma unroll
    for (int p = 0; p < 4; ++p)
        #pragma unroll
        for (int c = 0; c < 4; ++c) C[p][c] = 0ull;

    for (int j = 0; j < DH; ++j) {
        __syncthreads();   // previous compute done before overwriting Wsm
        // load W1 block for (i, j): [65, 64] contiguous floats
        {
            const float4* src = reinterpret_cast<const float4*>(
                W1 + (size_t)(i * DH + j) * DH * HID);
            float4* dst = reinterpret_cast<float4*>(&Wsm[0][0]);
            #pragma unroll
            for (int idx = tid; idx < DH * HID / 4; idx += THREADS)
                dst[idx] = src[idx];
        }
        __syncthreads();

        // per-row scalar s = a_h[b,i] * v_h[b,j]
        float sv[8];
        #pragma unroll
        for (int q = 0; q < 8; ++q) {
            int b = b0 + r0 + q;
            float vh = (j == 0) ? 1.0f : v[(size_t)b * DL + (j - 1)];
            sv[q] = a_col[r0 + q] * vh;
        }

        // u[p][c] = sum_k t[row_pair][k] * w[k][col]
        unsigned long long u[4][4];
        #pragma unroll
        for (int p = 0; p < 4; ++p)
            #pragma unroll
            for (int c = 0; c < 4; ++c) u[p][c] = 0ull;

        #pragma unroll 13
        for (int k = 0; k < DH; ++k) {
            // 8 t-values = 4 packed row-pairs (16B-aligned LDS)
            ulonglong2 ta = *reinterpret_cast<const ulonglong2*>(&Tsm[k][r0]);
            ulonglong2 tb = *reinterpret_cast<const ulonglong2*>(&Tsm[k][r0 + 4]);
            float4 w = *reinterpret_cast<const float4*>(&Wsm[k][h0]);
            unsigned long long w0 = pack2(w.x, w.x);
            unsigned long long w1 = pack2(w.y, w.y);
            unsigned long long w2 = pack2(w.z, w.z);
            unsigned long long w3 = pack2(w.w, w.w);
            fma2(u[0][0], ta.x, w0); fma2(u[0][1], ta.x, w1);
            fma2(u[0][2], ta.x, w2); fma2(u[0][3], ta.x, w3);
            fma2(u[1][0], ta.y, w0); fma2(u[1][1], ta.y, w1);
            fma2(u[1][2], ta.y, w2); fma2(u[1][3], ta.y, w3);
            fma2(u[2][0], tb.x, w0); fma2(u[2][1], tb.x, w1);
            fma2(u[2][2], tb.x, w2); fma2(u[2][3], tb.x, w3);
            fma2(u[3][0], tb.y, w0); fma2(u[3][1], tb.y, w1);
            fma2(u[3][2], tb.y, w2); fma2(u[3][3], tb.y, w3);
        }

        // C += s * u  (scale-after-reduce: 1 extra FMA per 65)
        unsigned long long s2[4];
        #pragma unroll
        for (int p = 0; p < 4; ++p) s2[p] = pack2(sv[2 * p], sv[2 * p + 1]);
        #pragma unroll
        for (int p = 0; p < 4; ++p)
            #pragma unroll
            for (int c = 0; c < 4; ++c) fma2(C[p][c], u[p][c], s2[p]);
    }

    // ---- store partials[i][b][h] ----
    #pragma unroll
    for (int p = 0; p < 4; ++p) {
        float lo[4], hi[4];
        #pragma unroll
        for (int c = 0; c < 4; ++c) unpack2(C[p][c], lo[c], hi[c]);
        size_t row_e = (size_t)i * BATCH + b0 + r0 + 2 * p;
        *reinterpret_cast<float4*>(&g_partials[row_e * HID + h0]) =
            make_float4(lo[0], lo[1], lo[2], lo[3]);
        *reinterpret_cast<float4*>(&g_partials[(row_e + 1) * HID + h0]) =
            make_float4(hi[0], hi[1], hi[2], hi[3]);
    }
}

// ============================================================================
// Kernel 2: reduce partials over i, then bias+tanh and the two 64x64 layers.
// grid = 512 (one block per batch row), block = 64 threads (one per channel).
// ============================================================================
__global__ void mlp_epilogue_kernel(const float* __restrict__ b1,
                                    const float* __restrict__ W2,
                                    const float* __restrict__ b2,
                                    const float* __restrict__ W3,
                                    const float* __restrict__ b3,
                                    float* __restrict__ out)
{
    const int b = blockIdx.x;
    const int h = threadIdx.x;
    __shared__ float h1s[HID];
    __shared__ float h2s[HID];

    float acc = 0.0f;
    #pragma unroll 5
    for (int i = 0; i < DH; ++i)
        acc += g_partials[((size_t)i * BATCH + b) * HID + h];

    h1s[h] = tanhf(acc + b1[h]);
    __syncthreads();

    float acc2 = b2[h];
    #pragma unroll
    for (int jj = 0; jj < HID; ++jj)
        acc2 = fmaf(h1s[jj], W2[(size_t)jj * HID + h], acc2);
    h2s[h] = tanhf(acc2);
    __syncthreads();

    float acc3 = b3[h];
    #pragma unroll
    for (int jj = 0; jj < HID; ++jj)
        acc3 = fmaf(h2s[jj], W3[(size_t)jj * DL + h], acc3);
    out[(size_t)b * DL + h] = tanhf(acc3);
}

// ============================================================================
extern "C" void kernel_launch(void* const* d_in, const int* in_sizes, int n_in,
                              void* d_out, int out_size)
{
    const float* l  = (const float*)d_in[0];
    const float* a  = (const float*)d_in[1];
    const float* v  = (const float*)d_in[2];
    const float* W1 = (const float*)d_in[3];
    const float* b1 = (const float*)d_in[4];
    const float* W2 = (const float*)d_in[5];
    const float* b2 = (const float*)d_in[6];
    const float* W3 = (const float*)d_in[7];
    const float* b3 = (const float*)d_in[8];
    float* out = (float*)d_out;

    dim3 grid1(NMT, DH);   // x = mtile (adjacent CTAs share i -> L2 reuse of W1)
    fusion_gemm_kernel<<<grid1, THREADS>>>(l, a, v, W1);
    mlp_epilogue_kernel<<<BATCH, HID>>>(b1, W2, b2, W3, b3, out);
}